// round 10
// baseline (speedup 1.0000x reference)
#include <cuda_runtime.h>

// Shapes (fixed for this problem)
#define B_   16
#define C_   256
#define HW_  4096
#define K_   1024
#define NPIX (B_ * HW_)          // 65536
#define ZQ_ELEMS (NPIX * C_)     // 16777216

// Scratch (no allocations allowed)
__device__ float  g_e2[K_];
__device__ int    g_idx[NPIX];
__device__ double g_loss;

// ---- packed f32x2 helpers (sm_103a FFMA2 path; bit-exact fp32) -------------
__device__ __forceinline__ unsigned long long pk2(float lo, float hi) {
    unsigned long long r;
    asm("mov.b64 %0, {%1, %2};" : "=l"(r) : "f"(lo), "f"(hi));
    return r;
}
__device__ __forceinline__ void upk2(float& lo, float& hi, unsigned long long v) {
    asm("mov.b64 {%0, %1}, %2;" : "=f"(lo), "=f"(hi) : "l"(v));
}
__device__ __forceinline__ void ffma2(unsigned long long& d,
                                      unsigned long long a,
                                      unsigned long long b) {
    asm("fma.rn.f32x2 %0, %1, %2, %3;" : "=l"(d) : "l"(a), "l"(b), "l"(d));
}

// ---------------------------------------------------------------------------
// Kernel 0: embedding squared norms + reset loss accumulator.
// ---------------------------------------------------------------------------
__global__ void vq_e2_kernel(const float* __restrict__ E) {
    int k = blockIdx.x;
    int lane = threadIdx.x;
    const float* row = E + (size_t)k * C_;
    float s = 0.f;
    #pragma unroll
    for (int c = lane; c < C_; c += 32) {
        float v = __ldg(row + c);
        s = fmaf(v, v, s);
    }
    #pragma unroll
    for (int off = 16; off; off >>= 1)
        s += __shfl_down_sync(0xffffffffu, s, off);
    if (lane == 0) g_e2[k] = s;
    if (k == 0 && lane == 0) g_loss = 0.0;
}

// ---------------------------------------------------------------------------
// Kernel 1: fused GEMM + argmin, FFMA2 (fma.rn.f32x2) mainloop.
// Block: 256 threads, tile = 128 pixels x 128 codes.
// Thread (tx,ty): pixels {2*ty + 32*i + h} (4 adjacent pairs -> LDS.64),
//                 codes  {tx + 16*j}, j=0..7.
// Distance d = ||e||^2 - 2 x.e  (x^2 per-pixel constant; dropped).
// All arithmetic remains exact fp32 -> argmin identical to scalar version.
// ---------------------------------------------------------------------------
#define TP 128   // pixels per block
#define KT 128   // codes per tile
#define CK 32    // c-chunk

__global__ __launch_bounds__(256, 2)
void vq_argmin_kernel(const float* __restrict__ X, const float* __restrict__ E) {
    __shared__ __align__(16) float xs[CK][TP];     // [c][pixel]
    __shared__ float es[CK][KT + 1];               // [c][code], pad: fill conflicts

    const int tid = threadIdx.x;
    const int tx = tid & 15;            // code group
    const int ty = tid >> 4;            // pixel-pair group
    const int n0 = blockIdx.x * TP;     // 4096 % 128 == 0 -> tile within one b
    const int b  = n0 / HW_;
    const int p0 = n0 % HW_;
    const float* xbase = X + (size_t)b * C_ * HW_ + p0;

    float bestv[8];                     // index = i*2 + h
    int   besti[8];
    #pragma unroll
    for (int i = 0; i < 8; ++i) { bestv[i] = 3.4e38f; besti[i] = 0; }

    for (int kt = 0; kt < K_; kt += KT) {
        unsigned long long acc2[4][8];  // packed pixel-pair accumulators
        #pragma unroll
        for (int i = 0; i < 4; ++i)
            #pragma unroll
            for (int j = 0; j < 8; ++j) acc2[i][j] = 0ull;

        for (int cc = 0; cc < C_; cc += CK) {
            __syncthreads();   // protect smem from previous chunk's readers
            // fill xs: 32x128 floats, coalesced
            #pragma unroll
            for (int l = 0; l < (CK * TP) / 256; ++l) {
                int ii = tid + l * 256;
                int c = ii >> 7, p = ii & 127;
                xs[c][p] = __ldg(xbase + (size_t)(cc + c) * HW_ + p);
            }
            // fill es: 128 codes x 32 c, transposed [c][k], conflict-free (pad)
            #pragma unroll
            for (int l = 0; l < (CK * KT) / 256; ++l) {
                int ii = tid + l * 256;
                int k = ii >> 5, c = ii & 31;
                es[c][k] = __ldg(E + (size_t)(kt + k) * C_ + (cc + c));
            }
            __syncthreads();

            #pragma unroll 4
            for (int c = 0; c < CK; ++c) {
                unsigned long long axp[4], ekk[8];
                #pragma unroll
                for (int i = 0; i < 4; ++i) {
                    float2 v = *reinterpret_cast<const float2*>(&xs[c][2 * ty + 32 * i]);
                    axp[i] = pk2(v.x, v.y);
                }
                #pragma unroll
                for (int j = 0; j < 8; ++j) {
                    float e = es[c][tx + j * 16];
                    ekk[j] = pk2(e, e);
                }
                #pragma unroll
                for (int i = 0; i < 4; ++i)
                    #pragma unroll
                    for (int j = 0; j < 8; ++j)
                        ffma2(acc2[i][j], axp[i], ekk[j]);
            }
        }

        // distance + running argmin (ties -> lower index, matching jnp.argmin)
        #pragma unroll
        for (int j = 0; j < 8; ++j) {
            int k = kt + tx + j * 16;
            float e2 = g_e2[k];
            #pragma unroll
            for (int i = 0; i < 4; ++i) {
                float a0, a1;
                upk2(a0, a1, acc2[i][j]);
                float d0 = fmaf(-2.f, a0, e2);
                float d1 = fmaf(-2.f, a1, e2);
                int s0 = i * 2, s1 = i * 2 + 1;
                if (d0 < bestv[s0] || (d0 == bestv[s0] && k < besti[s0])) {
                    bestv[s0] = d0; besti[s0] = k;
                }
                if (d1 < bestv[s1] || (d1 == bestv[s1] && k < besti[s1])) {
                    bestv[s1] = d1; besti[s1] = k;
                }
            }
        }
    }

    // reduce (minval, minidx) across the 16 code-group lanes (same ty)
    #pragma unroll
    for (int s = 0; s < 8; ++s) {
        float v = bestv[s];
        int   ix = besti[s];
        #pragma unroll
        for (int off = 8; off; off >>= 1) {
            float ov = __shfl_down_sync(0xffffffffu, v, off, 16);
            int   oi = __shfl_down_sync(0xffffffffu, ix, off, 16);
            if (ov < v || (ov == v && oi < ix)) { v = ov; ix = oi; }
        }
        if (tx == 0) {
            int i = s >> 1, h = s & 1;
            g_idx[n0 + 2 * ty + 32 * i + h] = ix;
        }
    }
}

// ---------------------------------------------------------------------------
// Kernel 2: gather z_q rows, transpose-write to (b,c,h,w), accumulate loss.
// ---------------------------------------------------------------------------
#define QP 32

__global__ __launch_bounds__(256)
void vq_gather_kernel(const float* __restrict__ X, const float* __restrict__ E,
                      float* __restrict__ out) {
    __shared__ float s[QP][C_ + 5];
    __shared__ int ids[QP];

    const int tid = threadIdx.x;
    const int n0 = blockIdx.x * QP;     // 4096 % 32 == 0 -> within one b
    if (tid < QP) ids[tid] = g_idx[n0 + tid];
    __syncthreads();

    #pragma unroll
    for (int l = 0; l < (QP * C_) / 256; ++l) {
        int ii = tid + l * 256;
        int q = ii >> 8, c = ii & 255;
        s[q][c] = __ldg(E + (size_t)ids[q] * C_ + c);
    }
    __syncthreads();

    const int b = n0 / HW_, p0 = n0 % HW_;
    const size_t obase = (size_t)b * C_ * HW_ + p0;
    const int q  = tid & 31;
    const int c0 = tid >> 5;            // 0..7

    float lsum = 0.f;
    #pragma unroll
    for (int l = 0; l < C_ / 8; ++l) {
        int c = c0 + l * 8;
        float zq = s[q][c];
        size_t a = obase + (size_t)c * HW_ + q;
        float xv = __ldg(X + a);
        out[a] = zq;
        float dd = xv - zq;
        lsum = fmaf(dd, dd, lsum);
    }

    // block reduce -> double atomic
    #pragma unroll
    for (int off = 16; off; off >>= 1)
        lsum += __shfl_down_sync(0xffffffffu, lsum, off);
    __shared__ float ws[8];
    if ((tid & 31) == 0) ws[tid >> 5] = lsum;
    __syncthreads();
    if (tid < 8) {
        float v = ws[tid];
        #pragma unroll
        for (int off = 4; off; off >>= 1)
            v += __shfl_down_sync(0xffu, v, off);
        if (tid == 0) atomicAdd(&g_loss, (double)v);
    }
}

// ---------------------------------------------------------------------------
// Kernel 3: finalize loss. quantization_loss = 2 * mean((zq - x)^2)
// ---------------------------------------------------------------------------
__global__ void vq_loss_kernel(float* __restrict__ out) {
    out[ZQ_ELEMS] = (float)(2.0 * g_loss / (double)ZQ_ELEMS);
}

// ---------------------------------------------------------------------------
extern "C" void kernel_launch(void* const* d_in, const int* in_sizes, int n_in,
                              void* d_out, int out_size) {
    const float* X = (const float*)d_in[0];   // x (16,256,64,64)
    const float* E = (const float*)d_in[1];   // embeddings (1024,256)
    float* out = (float*)d_out;

    vq_e2_kernel<<<K_, 32>>>(E);
    vq_argmin_kernel<<<NPIX / TP, 256>>>(X, E);
    vq_gather_kernel<<<NPIX / QP, 256>>>(X, E, out);
    if (out_size > ZQ_ELEMS)
        vq_loss_kernel<<<1, 1>>>(out);
}

// round 11
// speedup vs baseline: 1.0001x; 1.0001x over previous
#include <cuda_runtime.h>

// Shapes (fixed for this problem)
#define B_   16
#define C_   256
#define HW_  4096
#define K_   1024
#define NPIX (B_ * HW_)          // 65536
#define ZQ_ELEMS (NPIX * C_)     // 16777216

// Scratch (no allocations allowed)
__device__ float  g_e2[K_];
__device__ int    g_idx[NPIX];
__device__ double g_loss;

// ---- packed f32x2 helpers (sm_103a FFMA2 path; bit-exact fp32) -------------
__device__ __forceinline__ unsigned long long pk2(float lo, float hi) {
    unsigned long long r;
    asm("mov.b64 %0, {%1, %2};" : "=l"(r) : "f"(lo), "f"(hi));
    return r;
}
__device__ __forceinline__ void upk2(float& lo, float& hi, unsigned long long v) {
    asm("mov.b64 {%0, %1}, %2;" : "=f"(lo), "=f"(hi) : "l"(v));
}
__device__ __forceinline__ void ffma2(unsigned long long& d,
                                      unsigned long long a,
                                      unsigned long long b) {
    asm("fma.rn.f32x2 %0, %1, %2, %3;" : "=l"(d) : "l"(a), "l"(b), "l"(d));
}

// ---------------------------------------------------------------------------
// Kernel 0: embedding squared norms + reset loss accumulator.
// ---------------------------------------------------------------------------
__global__ void vq_e2_kernel(const float* __restrict__ E) {
    int k = blockIdx.x;
    int lane = threadIdx.x;
    const float* row = E + (size_t)k * C_;
    float s = 0.f;
    #pragma unroll
    for (int c = lane; c < C_; c += 32) {
        float v = __ldg(row + c);
        s = fmaf(v, v, s);
    }
    #pragma unroll
    for (int off = 16; off; off >>= 1)
        s += __shfl_down_sync(0xffffffffu, s, off);
    if (lane == 0) g_e2[k] = s;
    if (k == 0 && lane == 0) g_loss = 0.0;
}

// ---------------------------------------------------------------------------
// Kernel 1: fused GEMM + argmin, FFMA2 (fma.rn.f32x2) mainloop.
// Block: 256 threads, tile = 128 pixels x 128 codes.
// Thread (tx,ty): pixels {2*ty + 32*i + h} (4 adjacent pairs -> LDS.64),
//                 codes  {tx + 16*j}, j=0..7.
// Distance d = ||e||^2 - 2 x.e  (x^2 per-pixel constant; dropped).
// All arithmetic remains exact fp32 -> argmin identical to scalar version.
// ---------------------------------------------------------------------------
#define TP 128   // pixels per block
#define KT 128   // codes per tile
#define CK 32    // c-chunk

__global__ __launch_bounds__(256, 2)
void vq_argmin_kernel(const float* __restrict__ X, const float* __restrict__ E) {
    __shared__ __align__(16) float xs[CK][TP];     // [c][pixel]
    __shared__ float es[CK][KT + 1];               // [c][code], pad: fill conflicts

    const int tid = threadIdx.x;
    const int tx = tid & 15;            // code group
    const int ty = tid >> 4;            // pixel-pair group
    const int n0 = blockIdx.x * TP;     // 4096 % 128 == 0 -> tile within one b
    const int b  = n0 / HW_;
    const int p0 = n0 % HW_;
    const float* xbase = X + (size_t)b * C_ * HW_ + p0;

    float bestv[8];                     // index = i*2 + h
    int   besti[8];
    #pragma unroll
    for (int i = 0; i < 8; ++i) { bestv[i] = 3.4e38f; besti[i] = 0; }

    for (int kt = 0; kt < K_; kt += KT) {
        unsigned long long acc2[4][8];  // packed pixel-pair accumulators
        #pragma unroll
        for (int i = 0; i < 4; ++i)
            #pragma unroll
            for (int j = 0; j < 8; ++j) acc2[i][j] = 0ull;

        for (int cc = 0; cc < C_; cc += CK) {
            __syncthreads();   // protect smem from previous chunk's readers
            // fill xs: 32x128 floats, coalesced
            #pragma unroll
            for (int l = 0; l < (CK * TP) / 256; ++l) {
                int ii = tid + l * 256;
                int c = ii >> 7, p = ii & 127;
                xs[c][p] = __ldg(xbase + (size_t)(cc + c) * HW_ + p);
            }
            // fill es: 128 codes x 32 c, transposed [c][k], conflict-free (pad)
            #pragma unroll
            for (int l = 0; l < (CK * KT) / 256; ++l) {
                int ii = tid + l * 256;
                int k = ii >> 5, c = ii & 31;
                es[c][k] = __ldg(E + (size_t)(kt + k) * C_ + (cc + c));
            }
            __syncthreads();

            #pragma unroll 4
            for (int c = 0; c < CK; ++c) {
                unsigned long long axp[4], ekk[8];
                #pragma unroll
                for (int i = 0; i < 4; ++i) {
                    float2 v = *reinterpret_cast<const float2*>(&xs[c][2 * ty + 32 * i]);
                    axp[i] = pk2(v.x, v.y);
                }
                #pragma unroll
                for (int j = 0; j < 8; ++j) {
                    float e = es[c][tx + j * 16];
                    ekk[j] = pk2(e, e);
                }
                #pragma unroll
                for (int i = 0; i < 4; ++i)
                    #pragma unroll
                    for (int j = 0; j < 8; ++j)
                        ffma2(acc2[i][j], axp[i], ekk[j]);
            }
        }

        // distance + running argmin (ties -> lower index, matching jnp.argmin)
        #pragma unroll
        for (int j = 0; j < 8; ++j) {
            int k = kt + tx + j * 16;
            float e2 = g_e2[k];
            #pragma unroll
            for (int i = 0; i < 4; ++i) {
                float a0, a1;
                upk2(a0, a1, acc2[i][j]);
                float d0 = fmaf(-2.f, a0, e2);
                float d1 = fmaf(-2.f, a1, e2);
                int s0 = i * 2, s1 = i * 2 + 1;
                if (d0 < bestv[s0] || (d0 == bestv[s0] && k < besti[s0])) {
                    bestv[s0] = d0; besti[s0] = k;
                }
                if (d1 < bestv[s1] || (d1 == bestv[s1] && k < besti[s1])) {
                    bestv[s1] = d1; besti[s1] = k;
                }
            }
        }
    }

    // reduce (minval, minidx) across the 16 code-group lanes (same ty)
    #pragma unroll
    for (int s = 0; s < 8; ++s) {
        float v = bestv[s];
        int   ix = besti[s];
        #pragma unroll
        for (int off = 8; off; off >>= 1) {
            float ov = __shfl_down_sync(0xffffffffu, v, off, 16);
            int   oi = __shfl_down_sync(0xffffffffu, ix, off, 16);
            if (ov < v || (ov == v && oi < ix)) { v = ov; ix = oi; }
        }
        if (tx == 0) {
            int i = s >> 1, h = s & 1;
            g_idx[n0 + 2 * ty + 32 * i + h] = ix;
        }
    }
}

// ---------------------------------------------------------------------------
// Kernel 2: gather z_q rows, transpose-write to (b,c,h,w), accumulate loss.
// ---------------------------------------------------------------------------
#define QP 32

__global__ __launch_bounds__(256)
void vq_gather_kernel(const float* __restrict__ X, const float* __restrict__ E,
                      float* __restrict__ out) {
    __shared__ float s[QP][C_ + 5];
    __shared__ int ids[QP];

    const int tid = threadIdx.x;
    const int n0 = blockIdx.x * QP;     // 4096 % 32 == 0 -> within one b
    if (tid < QP) ids[tid] = g_idx[n0 + tid];
    __syncthreads();

    #pragma unroll
    for (int l = 0; l < (QP * C_) / 256; ++l) {
        int ii = tid + l * 256;
        int q = ii >> 8, c = ii & 255;
        s[q][c] = __ldg(E + (size_t)ids[q] * C_ + c);
    }
    __syncthreads();

    const int b = n0 / HW_, p0 = n0 % HW_;
    const size_t obase = (size_t)b * C_ * HW_ + p0;
    const int q  = tid & 31;
    const int c0 = tid >> 5;            // 0..7

    float lsum = 0.f;
    #pragma unroll
    for (int l = 0; l < C_ / 8; ++l) {
        int c = c0 + l * 8;
        float zq = s[q][c];
        size_t a = obase + (size_t)c * HW_ + q;
        float xv = __ldg(X + a);
        out[a] = zq;
        float dd = xv - zq;
        lsum = fmaf(dd, dd, lsum);
    }

    // block reduce -> double atomic
    #pragma unroll
    for (int off = 16; off; off >>= 1)
        lsum += __shfl_down_sync(0xffffffffu, lsum, off);
    __shared__ float ws[8];
    if ((tid & 31) == 0) ws[tid >> 5] = lsum;
    __syncthreads();
    if (tid < 8) {
        float v = ws[tid];
        #pragma unroll
        for (int off = 4; off; off >>= 1)
            v += __shfl_down_sync(0xffu, v, off);
        if (tid == 0) atomicAdd(&g_loss, (double)v);
    }
}

// ---------------------------------------------------------------------------
// Kernel 3: finalize loss. quantization_loss = 2 * mean((zq - x)^2)
// ---------------------------------------------------------------------------
__global__ void vq_loss_kernel(float* __restrict__ out) {
    out[ZQ_ELEMS] = (float)(2.0 * g_loss / (double)ZQ_ELEMS);
}

// ---------------------------------------------------------------------------
extern "C" void kernel_launch(void* const* d_in, const int* in_sizes, int n_in,
                              void* d_out, int out_size) {
    const float* X = (const float*)d_in[0];   // x (16,256,64,64)
    const float* E = (const float*)d_in[1];   // embeddings (1024,256)
    float* out = (float*)d_out;

    vq_e2_kernel<<<K_, 32>>>(E);
    vq_argmin_kernel<<<NPIX / TP, 256>>>(X, E);
    vq_gather_kernel<<<NPIX / QP, 256>>>(X, E, out);
    if (out_size > ZQ_ELEMS)
        vq_loss_kernel<<<1, 1>>>(out);
}

// round 12
// speedup vs baseline: 1.0007x; 1.0006x over previous
#include <cuda_runtime.h>

// Shapes (fixed for this problem)
#define B_   16
#define C_   256
#define HW_  4096
#define K_   1024
#define NPIX (B_ * HW_)          // 65536
#define ZQ_ELEMS (NPIX * C_)     // 16777216

// Scratch (no allocations allowed)
__device__ float  g_e2[K_];
__device__ int    g_idx[NPIX];
__device__ double g_loss;

// ---- packed f32x2 helpers (sm_103a FFMA2 path; bit-exact fp32) -------------
__device__ __forceinline__ unsigned long long pk2(float lo, float hi) {
    unsigned long long r;
    asm("mov.b64 %0, {%1, %2};" : "=l"(r) : "f"(lo), "f"(hi));
    return r;
}
__device__ __forceinline__ void upk2(float& lo, float& hi, unsigned long long v) {
    asm("mov.b64 {%0, %1}, %2;" : "=f"(lo), "=f"(hi) : "l"(v));
}
__device__ __forceinline__ void ffma2(unsigned long long& d,
                                      unsigned long long a,
                                      unsigned long long b) {
    asm("fma.rn.f32x2 %0, %1, %2, %3;" : "=l"(d) : "l"(a), "l"(b), "l"(d));
}

// ---------------------------------------------------------------------------
// Kernel 0: embedding squared norms + reset loss accumulator.
// ---------------------------------------------------------------------------
__global__ void vq_e2_kernel(const float* __restrict__ E) {
    int k = blockIdx.x;
    int lane = threadIdx.x;
    const float* row = E + (size_t)k * C_;
    float s = 0.f;
    #pragma unroll
    for (int c = lane; c < C_; c += 32) {
        float v = __ldg(row + c);
        s = fmaf(v, v, s);
    }
    #pragma unroll
    for (int off = 16; off; off >>= 1)
        s += __shfl_down_sync(0xffffffffu, s, off);
    if (lane == 0) g_e2[k] = s;
    if (k == 0 && lane == 0) g_loss = 0.0;
}

// ---------------------------------------------------------------------------
// Kernel 1: fused GEMM + argmin, FFMA2 (fma.rn.f32x2) mainloop.
// Block: 256 threads, tile = 128 pixels x 128 codes.
// Thread (tx,ty): pixels {2*ty + 32*i + h} (4 adjacent pairs -> LDS.64),
//                 codes  {tx + 16*j}, j=0..7.
// Distance d = ||e||^2 - 2 x.e  (x^2 per-pixel constant; dropped).
// All arithmetic remains exact fp32 -> argmin identical to scalar version.
// ---------------------------------------------------------------------------
#define TP 128   // pixels per block
#define KT 128   // codes per tile
#define CK 32    // c-chunk

__global__ __launch_bounds__(256, 2)
void vq_argmin_kernel(const float* __restrict__ X, const float* __restrict__ E) {
    __shared__ __align__(16) float xs[CK][TP];     // [c][pixel]
    __shared__ float es[CK][KT + 1];               // [c][code], pad: fill conflicts

    const int tid = threadIdx.x;
    const int tx = tid & 15;            // code group
    const int ty = tid >> 4;            // pixel-pair group
    const int n0 = blockIdx.x * TP;     // 4096 % 128 == 0 -> tile within one b
    const int b  = n0 / HW_;
    const int p0 = n0 % HW_;
    const float* xbase = X + (size_t)b * C_ * HW_ + p0;

    float bestv[8];                     // index = i*2 + h
    int   besti[8];
    #pragma unroll
    for (int i = 0; i < 8; ++i) { bestv[i] = 3.4e38f; besti[i] = 0; }

    for (int kt = 0; kt < K_; kt += KT) {
        unsigned long long acc2[4][8];  // packed pixel-pair accumulators
        #pragma unroll
        for (int i = 0; i < 4; ++i)
            #pragma unroll
            for (int j = 0; j < 8; ++j) acc2[i][j] = 0ull;

        for (int cc = 0; cc < C_; cc += CK) {
            __syncthreads();   // protect smem from previous chunk's readers
            // fill xs: 32x128 floats, coalesced
            #pragma unroll
            for (int l = 0; l < (CK * TP) / 256; ++l) {
                int ii = tid + l * 256;
                int c = ii >> 7, p = ii & 127;
                xs[c][p] = __ldg(xbase + (size_t)(cc + c) * HW_ + p);
            }
            // fill es: 128 codes x 32 c, transposed [c][k], conflict-free (pad)
            #pragma unroll
            for (int l = 0; l < (CK * KT) / 256; ++l) {
                int ii = tid + l * 256;
                int k = ii >> 5, c = ii & 31;
                es[c][k] = __ldg(E + (size_t)(kt + k) * C_ + (cc + c));
            }
            __syncthreads();

            #pragma unroll 4
            for (int c = 0; c < CK; ++c) {
                unsigned long long axp[4], ekk[8];
                #pragma unroll
                for (int i = 0; i < 4; ++i) {
                    float2 v = *reinterpret_cast<const float2*>(&xs[c][2 * ty + 32 * i]);
                    axp[i] = pk2(v.x, v.y);
                }
                #pragma unroll
                for (int j = 0; j < 8; ++j) {
                    float e = es[c][tx + j * 16];
                    ekk[j] = pk2(e, e);
                }
                #pragma unroll
                for (int i = 0; i < 4; ++i)
                    #pragma unroll
                    for (int j = 0; j < 8; ++j)
                        ffma2(acc2[i][j], axp[i], ekk[j]);
            }
        }

        // distance + running argmin (ties -> lower index, matching jnp.argmin)
        #pragma unroll
        for (int j = 0; j < 8; ++j) {
            int k = kt + tx + j * 16;
            float e2 = g_e2[k];
            #pragma unroll
            for (int i = 0; i < 4; ++i) {
                float a0, a1;
                upk2(a0, a1, acc2[i][j]);
                float d0 = fmaf(-2.f, a0, e2);
                float d1 = fmaf(-2.f, a1, e2);
                int s0 = i * 2, s1 = i * 2 + 1;
                if (d0 < bestv[s0] || (d0 == bestv[s0] && k < besti[s0])) {
                    bestv[s0] = d0; besti[s0] = k;
                }
                if (d1 < bestv[s1] || (d1 == bestv[s1] && k < besti[s1])) {
                    bestv[s1] = d1; besti[s1] = k;
                }
            }
        }
    }

    // reduce (minval, minidx) across the 16 code-group lanes (same ty)
    #pragma unroll
    for (int s = 0; s < 8; ++s) {
        float v = bestv[s];
        int   ix = besti[s];
        #pragma unroll
        for (int off = 8; off; off >>= 1) {
            float ov = __shfl_down_sync(0xffffffffu, v, off, 16);
            int   oi = __shfl_down_sync(0xffffffffu, ix, off, 16);
            if (ov < v || (ov == v && oi < ix)) { v = ov; ix = oi; }
        }
        if (tx == 0) {
            int i = s >> 1, h = s & 1;
            g_idx[n0 + 2 * ty + 32 * i + h] = ix;
        }
    }
}

// ---------------------------------------------------------------------------
// Kernel 2: gather z_q rows, transpose-write to (b,c,h,w), accumulate loss.
// ---------------------------------------------------------------------------
#define QP 32

__global__ __launch_bounds__(256)
void vq_gather_kernel(const float* __restrict__ X, const float* __restrict__ E,
                      float* __restrict__ out) {
    __shared__ float s[QP][C_ + 5];
    __shared__ int ids[QP];

    const int tid = threadIdx.x;
    const int n0 = blockIdx.x * QP;     // 4096 % 32 == 0 -> within one b
    if (tid < QP) ids[tid] = g_idx[n0 + tid];
    __syncthreads();

    #pragma unroll
    for (int l = 0; l < (QP * C_) / 256; ++l) {
        int ii = tid + l * 256;
        int q = ii >> 8, c = ii & 255;
        s[q][c] = __ldg(E + (size_t)ids[q] * C_ + c);
    }
    __syncthreads();

    const int b = n0 / HW_, p0 = n0 % HW_;
    const size_t obase = (size_t)b * C_ * HW_ + p0;
    const int q  = tid & 31;
    const int c0 = tid >> 5;            // 0..7

    float lsum = 0.f;
    #pragma unroll
    for (int l = 0; l < C_ / 8; ++l) {
        int c = c0 + l * 8;
        float zq = s[q][c];
        size_t a = obase + (size_t)c * HW_ + q;
        float xv = __ldg(X + a);
        out[a] = zq;
        float dd = xv - zq;
        lsum = fmaf(dd, dd, lsum);
    }

    // block reduce -> double atomic
    #pragma unroll
    for (int off = 16; off; off >>= 1)
        lsum += __shfl_down_sync(0xffffffffu, lsum, off);
    __shared__ float ws[8];
    if ((tid & 31) == 0) ws[tid >> 5] = lsum;
    __syncthreads();
    if (tid < 8) {
        float v = ws[tid];
        #pragma unroll
        for (int off = 4; off; off >>= 1)
            v += __shfl_down_sync(0xffu, v, off);
        if (tid == 0) atomicAdd(&g_loss, (double)v);
    }
}

// ---------------------------------------------------------------------------
// Kernel 3: finalize loss. quantization_loss = 2 * mean((zq - x)^2)
// ---------------------------------------------------------------------------
__global__ void vq_loss_kernel(float* __restrict__ out) {
    out[ZQ_ELEMS] = (float)(2.0 * g_loss / (double)ZQ_ELEMS);
}

// ---------------------------------------------------------------------------
extern "C" void kernel_launch(void* const* d_in, const int* in_sizes, int n_in,
                              void* d_out, int out_size) {
    const float* X = (const float*)d_in[0];   // x (16,256,64,64)
    const float* E = (const float*)d_in[1];   // embeddings (1024,256)
    float* out = (float*)d_out;

    vq_e2_kernel<<<K_, 32>>>(E);
    vq_argmin_kernel<<<NPIX / TP, 256>>>(X, E);
    vq_gather_kernel<<<NPIX / QP, 256>>>(X, E, out);
    if (out_size > ZQ_ELEMS)
        vq_loss_kernel<<<1, 1>>>(out);
}

// round 16
// speedup vs baseline: 1.1266x; 1.1258x over previous
#include <cuda_runtime.h>
#include <cuda_bf16.h>
#include <cstdint>

// Shapes (fixed for this problem)
#define B_   16
#define C_   256
#define HW_  4096
#define K_   1024
#define NPIX (B_ * HW_)          // 65536
#define ZQ_ELEMS (NPIX * C_)     // 16777216

// ---------------- scratch (static device arrays; no allocations) ------------
__device__ float  g_e2[K_];
__device__ int    g_idx[NPIX];
__device__ double g_loss;
__device__ __align__(16) __nv_bfloat16 g_xhi[(size_t)NPIX * C_];
__device__ __align__(16) __nv_bfloat16 g_xlo[(size_t)NPIX * C_];
__device__ __align__(16) __nv_bfloat16 g_ehi[K_ * C_];
__device__ __align__(16) __nv_bfloat16 g_elo[K_ * C_];
__device__ int g_rcnt;
__device__ int g_rpix[NPIX];

// ---------------- PTX helpers (sm_80+ features only; no 'a'-gated ops) ------
__device__ __forceinline__ uint32_t smem_u32(const void* p) {
    uint32_t a;
    asm("{ .reg .u64 t; cvta.to.shared.u64 t, %1; cvt.u32.u64 %0, t; }"
        : "=r"(a) : "l"(p));
    return a;
}
__device__ __forceinline__ void cp16(uint32_t dst, const void* src) {
    asm volatile("cp.async.cg.shared.global [%0], [%1], 16;"
                 :: "r"(dst), "l"(src) : "memory");
}
__device__ __forceinline__ void cp_commit() {
    asm volatile("cp.async.commit_group;" ::: "memory");
}
__device__ __forceinline__ void cp_wait1() {
    asm volatile("cp.async.wait_group 1;" ::: "memory");
}

// ---------------------------------------------------------------------------
// Prep 1: transpose x (b,c,hw) -> [pixel][c] bf16 hi/lo split.
// ---------------------------------------------------------------------------
__global__ __launch_bounds__(256)
void vq_prepx_kernel(const float* __restrict__ X) {
    __shared__ float tile[32][33];
    const int bi = blockIdx.x;
    const int b  = bi >> 10;
    const int t  = bi & 1023;
    const int c0 = (t >> 7) << 5;
    const int p0 = (t & 127) << 5;
    const int tid = threadIdx.x;

    #pragma unroll
    for (int it = 0; it < 4; ++it) {
        int idx = tid + it * 256;
        int c = idx >> 5, p = idx & 31;
        tile[c][p] = __ldg(X + ((size_t)b * C_ + c0 + c) * HW_ + p0 + p);
    }
    __syncthreads();
    #pragma unroll
    for (int it = 0; it < 4; ++it) {
        int idx = tid + it * 256;
        int p = idx >> 5, c = idx & 31;
        float v = tile[c][p];
        __nv_bfloat16 h = __float2bfloat16(v);
        __nv_bfloat16 l = __float2bfloat16(v - __bfloat162float(h));
        size_t dst = (size_t)(b * HW_ + p0 + p) * C_ + c0 + c;
        g_xhi[dst] = h;
        g_xlo[dst] = l;
    }
}

// ---------------------------------------------------------------------------
// Prep 2: embeddings -> bf16 hi/lo + fp32 squared norms; reset counters.
// ---------------------------------------------------------------------------
__global__ __launch_bounds__(256)
void vq_prepe_kernel(const float* __restrict__ E) {
    const int k = blockIdx.x, c = threadIdx.x;
    float v = __ldg(E + k * C_ + c);
    __nv_bfloat16 h = __float2bfloat16(v);
    g_ehi[k * C_ + c] = h;
    g_elo[k * C_ + c] = __float2bfloat16(v - __bfloat162float(h));
    float s = v * v;
    #pragma unroll
    for (int off = 16; off; off >>= 1)
        s += __shfl_down_sync(0xffffffffu, s, off);
    __shared__ float ws[8];
    if ((c & 31) == 0) ws[c >> 5] = s;
    __syncthreads();
    if (c < 8) {
        float t = ws[c];
        #pragma unroll
        for (int off = 4; off; off >>= 1)
            t += __shfl_down_sync(0xffu, t, off);
        if (c == 0) g_e2[k] = t;
    }
    if (k == 0 && c == 0) { g_loss = 0.0; g_rcnt = 0; }
}

// ---------------------------------------------------------------------------
// Main kernel: mma.sync bf16 split-GEMM + (v1,k1,v2) argmin with margin.
// Block: 256 threads = 8 warps (2 M x 4 N). Block tile: 128 pixels.
// 4 N-iterations of 256 codes; K = 3 bf16 passes x 256 dims, chunks of 64,
// cp.async double-buffered B. Distance d = e2[k] - 2 x.e.
// ---------------------------------------------------------------------------
#define GTP 128
// SMEM layout (bytes)
#define SM_A    0          // 2 splits x 65536 (128 p x 256 c bf16, swizzled)
#define SM_B    131072     // 2 bufs x 32768 (256 codes x 64 c bf16, swizzled)
#define SM_E2   196608     // 4096
#define SM_MV1  200704     // 128*4 floats
#define SM_MK1  202752
#define SM_MV2  204800
#define SM_TOT  206848

#define RESC_W 0.06f

__device__ __forceinline__ void load_b_chunk(uint32_t sb, int tid, int q, int buf) {
    const int nt = q >> 3, kc = (q >> 1) & 3, split = q & 1;
    const __nv_bfloat16* src = split ? g_elo : g_ehi;
    #pragma unroll
    for (int it = 0; it < 8; ++it) {
        int v = tid + it * 256;
        int row = v >> 3, g = v & 7;
        uint32_t gp = (uint32_t)(g ^ (row & 7));
        uint32_t dst = sb + SM_B + (uint32_t)buf * 32768u
                     + (uint32_t)row * 128u + gp * 16u;
        cp16(dst, src + ((size_t)(nt * 256 + row) * C_ + kc * 64 + g * 8));
    }
}

__global__ __launch_bounds__(256, 1)
void vq_gemm_kernel() {
    extern __shared__ char sm[];
    const uint32_t sb = smem_u32(sm);
    const int tid = threadIdx.x;
    const int lane = tid & 31, wid = tid >> 5;
    const int warp_m = wid >> 2, warp_n = wid & 3;
    const int n0 = blockIdx.x * GTP;

    // prologue: async-issue first two B chunks
    load_b_chunk(sb, tid, 0, 0); cp_commit();
    load_b_chunk(sb, tid, 1, 1); cp_commit();

    // stage A (hi + lo): [128 p][256 c] bf16, XOR-swizzled 16B granules
    #pragma unroll
    for (int it = 0; it < 32; ++it) {
        int v = tid + it * 256;          // 0..8191
        int s = v >> 12, rem = v & 4095;
        int p = rem >> 5, g = rem & 31;
        uint32_t gp = (uint32_t)((g & 24) | ((g ^ p) & 7));
        const uint4* src = (const uint4*)(s ? g_xlo : g_xhi);
        *(uint4*)(sm + SM_A + s * 65536 + p * 512 + gp * 16) =
            src[(size_t)(n0 + p) * 32 + g];
    }
    // stage e2
    for (int i = tid; i < K_; i += 256)
        ((float*)(sm + SM_E2))[i] = g_e2[i];

    float C[4][8][4];
    float sv1[8], sv2[8]; int sk1[8];
    #pragma unroll
    for (int i = 0; i < 8; ++i) { sv1[i] = 3.4e38f; sv2[i] = 3.4e38f; sk1[i] = 0; }

    int q = 0;
    #pragma unroll 1
    for (int nt = 0; nt < 4; ++nt) {
        #pragma unroll
        for (int mt = 0; mt < 4; ++mt)
            #pragma unroll
            for (int n8 = 0; n8 < 8; ++n8)
                #pragma unroll
                for (int e = 0; e < 4; ++e) C[mt][n8][e] = 0.f;

        #pragma unroll 1
        for (int kc = 0; kc < 4; ++kc) {
            #pragma unroll 1
            for (int split = 0; split < 2; ++split) {
                const int buf = q & 1;
                cp_wait1();
                __syncthreads();                 // chunk q ready for all warps
                const int npass = split ? 1 : 2; // hi-B: Ahi,Alo; lo-B: Ahi
                #pragma unroll 1
                for (int pass = 0; pass < npass; ++pass) {
                    const int asplit = (split == 0) ? pass : 0;
                    const uint32_t abase = sb + SM_A + (uint32_t)asplit * 65536u;
                    const uint32_t bbase = sb + SM_B + (uint32_t)buf * 32768u;
                    #pragma unroll
                    for (int kk = 0; kk < 4; ++kk) {
                        uint32_t a[4][4];
                        #pragma unroll
                        for (int mt = 0; mt < 4; ++mt) {
                            int p = warp_m * 64 + mt * 16 + (lane & 15);
                            int g = kc * 8 + kk * 2 + (lane >> 4);
                            uint32_t gp = (uint32_t)((g & 24) | ((g ^ p) & 7));
                            uint32_t addr = abase + (uint32_t)p * 512u + gp * 16u;
                            asm volatile(
                                "ldmatrix.sync.aligned.m8n8.x4.shared.b16 "
                                "{%0,%1,%2,%3}, [%4];"
                                : "=r"(a[mt][0]), "=r"(a[mt][1]),
                                  "=r"(a[mt][2]), "=r"(a[mt][3])
                                : "r"(addr));
                        }
                        uint32_t b[8][2];
                        #pragma unroll
                        for (int nq = 0; nq < 4; ++nq) {
                            int n = warp_n * 64 + nq * 16
                                  + ((lane >> 4) << 3) + (lane & 7);
                            int g = kk * 2 + ((lane >> 3) & 1);
                            uint32_t gp = (uint32_t)(g ^ (n & 7));
                            uint32_t addr = bbase + (uint32_t)n * 128u + gp * 16u;
                            asm volatile(
                                "ldmatrix.sync.aligned.m8n8.x4.shared.b16 "
                                "{%0,%1,%2,%3}, [%4];"
                                : "=r"(b[2 * nq][0]), "=r"(b[2 * nq][1]),
                                  "=r"(b[2 * nq + 1][0]), "=r"(b[2 * nq + 1][1])
                                : "r"(addr));
                        }
                        #pragma unroll
                        for (int mt = 0; mt < 4; ++mt)
                            #pragma unroll
                            for (int n8 = 0; n8 < 8; ++n8)
                                asm volatile(
                                    "mma.sync.aligned.m16n8k16.row.col.f32.bf16.bf16.f32 "
                                    "{%0,%1,%2,%3}, {%4,%5,%6,%7}, {%8,%9}, {%0,%1,%2,%3};"
                                    : "+f"(C[mt][n8][0]), "+f"(C[mt][n8][1]),
                                      "+f"(C[mt][n8][2]), "+f"(C[mt][n8][3])
                                    : "r"(a[mt][0]), "r"(a[mt][1]),
                                      "r"(a[mt][2]), "r"(a[mt][3]),
                                      "r"(b[n8][0]), "r"(b[n8][1]));
                    }
                }
                __syncthreads();                 // all done reading buf[q&1]
                if (q + 2 < 32) { load_b_chunk(sb, tid, q + 2, buf); cp_commit(); }
                ++q;
            }
        }

        // epilogue for this 256-code N-iteration
        const float* e2s = (const float*)(sm + SM_E2);
        #pragma unroll
        for (int mt = 0; mt < 4; ++mt) {
            #pragma unroll
            for (int n8 = 0; n8 < 8; ++n8) {
                int k = nt * 256 + warp_n * 64 + n8 * 8 + (lane & 3) * 2;
                float e20 = e2s[k], e21 = e2s[k + 1];
                #pragma unroll
                for (int h = 0; h < 2; ++h) {
                    int s = mt * 2 + h;
                    float d0 = fmaf(-2.f, C[mt][n8][2 * h], e20);
                    float d1 = fmaf(-2.f, C[mt][n8][2 * h + 1], e21);
                    if (d0 < sv1[s]) { sv2[s] = sv1[s]; sv1[s] = d0; sk1[s] = k; }
                    else if (d0 < sv2[s]) sv2[s] = d0;
                    if (d1 < sv1[s]) { sv2[s] = sv1[s]; sv1[s] = d1; sk1[s] = k + 1; }
                    else if (d1 < sv2[s]) sv2[s] = d1;
                }
            }
        }
    }

    // merge (v1,k1,v2) across the 4 lanes sharing each pixel row
    #pragma unroll
    for (int s = 0; s < 8; ++s) {
        float v1 = sv1[s], v2 = sv2[s]; int k1 = sk1[s];
        #pragma unroll
        for (int off = 1; off <= 2; off <<= 1) {
            float o1 = __shfl_xor_sync(0xffffffffu, v1, off);
            int   ok = __shfl_xor_sync(0xffffffffu, k1, off);
            float o2 = __shfl_xor_sync(0xffffffffu, v2, off);
            float m = fmaxf(v1, o1);
            if (o1 < v1 || (o1 == v1 && ok < k1)) { v1 = o1; k1 = ok; }
            v2 = fminf(fminf(v2, o2), m);
        }
        if ((lane & 3) == 0) {
            int pix = warp_m * 64 + (s >> 1) * 16 + (s & 1) * 8 + (lane >> 2);
            ((float*)(sm + SM_MV1))[pix * 4 + warp_n] = v1;
            ((int*)  (sm + SM_MK1))[pix * 4 + warp_n] = k1;
            ((float*)(sm + SM_MV2))[pix * 4 + warp_n] = v2;
        }
    }
    __syncthreads();
    // final merge across the 4 warp_n columns; emit index + rescue flag
    if (tid < GTP) {
        float v1 = 3.4e38f, v2 = 3.4e38f; int k1 = 0;
        #pragma unroll
        for (int w = 0; w < 4; ++w) {
            float o1 = ((float*)(sm + SM_MV1))[tid * 4 + w];
            int   ok = ((int*)  (sm + SM_MK1))[tid * 4 + w];
            float o2 = ((float*)(sm + SM_MV2))[tid * 4 + w];
            float m = fmaxf(v1, o1);
            if (o1 < v1 || (o1 == v1 && ok < k1)) { v1 = o1; k1 = ok; }
            v2 = fminf(fminf(v2, o2), m);
        }
        int pix = n0 + tid;
        g_idx[pix] = k1;
        if (v2 - v1 < RESC_W) {
            int r = atomicAdd(&g_rcnt, 1);
            g_rpix[r] = pix;
        }
    }
}

// ---------------------------------------------------------------------------
// Rescue: FULL exact fp32 scan (all 1024 codes) for near-margin pixels.
// Same fmaf-chain arithmetic as the proven scalar kernel.
// ---------------------------------------------------------------------------
__global__ __launch_bounds__(256)
void vq_rescue_kernel(const float* __restrict__ X, const float* __restrict__ E) {
    __shared__ float xr[C_];
    __shared__ float bv[256];
    __shared__ int   bk[256];
    const int t = threadIdx.x;

    for (int r = blockIdx.x; r < g_rcnt; r += gridDim.x) {
        const int pix = g_rpix[r];
        const int b = pix / HW_, hw = pix % HW_;
        if (t < C_) xr[t] = __ldg(X + ((size_t)b * C_ + t) * HW_ + hw);
        __syncthreads();

        float best = 3.4e38f; int bestk = 0;
        #pragma unroll 1
        for (int kk = 0; kk < 4; ++kk) {
            int k = t + kk * 256;
            const float* e = E + (size_t)k * C_;
            float acc = 0.f;
            #pragma unroll 8
            for (int c = 0; c < C_; ++c)
                acc = fmaf(xr[c], __ldg(e + c), acc);
            float d = fmaf(-2.f, acc, g_e2[k]);
            if (d < best || (d == best && k < bestk)) { best = d; bestk = k; }
        }
        bv[t] = best; bk[t] = bestk;
        __syncthreads();
        for (int s = 128; s; s >>= 1) {
            if (t < s) {
                if (bv[t + s] < bv[t] ||
                    (bv[t + s] == bv[t] && bk[t + s] < bk[t])) {
                    bv[t] = bv[t + s]; bk[t] = bk[t + s];
                }
            }
            __syncthreads();
        }
        if (t == 0) g_idx[pix] = bk[0];
        __syncthreads();
    }
}

// ---------------------------------------------------------------------------
// Gather z_q, transpose-write, accumulate loss.
// ---------------------------------------------------------------------------
#define QP 32

__global__ __launch_bounds__(256)
void vq_gather_kernel(const float* __restrict__ X, const float* __restrict__ E,
                      float* __restrict__ out) {
    __shared__ float s[QP][C_ + 5];
    __shared__ int ids[QP];

    const int tid = threadIdx.x;
    const int n0 = blockIdx.x * QP;
    if (tid < QP) ids[tid] = g_idx[n0 + tid];
    __syncthreads();

    #pragma unroll
    for (int l = 0; l < (QP * C_) / 256; ++l) {
        int ii = tid + l * 256;
        int q = ii >> 8, c = ii & 255;
        s[q][c] = __ldg(E + (size_t)ids[q] * C_ + c);
    }
    __syncthreads();

    const int b = n0 / HW_, p0 = n0 % HW_;
    const size_t obase = (size_t)b * C_ * HW_ + p0;
    const int q  = tid & 31;
    const int c0 = tid >> 5;

    float lsum = 0.f;
    #pragma unroll
    for (int l = 0; l < C_ / 8; ++l) {
        int c = c0 + l * 8;
        float zq = s[q][c];
        size_t a = obase + (size_t)c * HW_ + q;
        float xv = __ldg(X + a);
        out[a] = zq;
        float dd = xv - zq;
        lsum = fmaf(dd, dd, lsum);
    }

    #pragma unroll
    for (int off = 16; off; off >>= 1)
        lsum += __shfl_down_sync(0xffffffffu, lsum, off);
    __shared__ float ws[8];
    if ((tid & 31) == 0) ws[tid >> 5] = lsum;
    __syncthreads();
    if (tid < 8) {
        float v = ws[tid];
        #pragma unroll
        for (int off = 4; off; off >>= 1)
            v += __shfl_down_sync(0xffu, v, off);
        if (tid == 0) atomicAdd(&g_loss, (double)v);
    }
}

__global__ void vq_loss_kernel(float* __restrict__ out) {
    out[ZQ_ELEMS] = (float)(2.0 * g_loss / (double)ZQ_ELEMS);
}

// ---------------------------------------------------------------------------
extern "C" void kernel_launch(void* const* d_in, const int* in_sizes, int n_in,
                              void* d_out, int out_size) {
    const float* X = (const float*)d_in[0];
    const float* E = (const float*)d_in[1];
    float* out = (float*)d_out;

    cudaFuncSetAttribute(vq_gemm_kernel,
                         cudaFuncAttributeMaxDynamicSharedMemorySize, SM_TOT);

    vq_prepx_kernel<<<16384, 256>>>(X);
    vq_prepe_kernel<<<K_, 256>>>(E);
    vq_gemm_kernel<<<NPIX / GTP, 256, SM_TOT>>>();
    vq_rescue_kernel<<<1024, 256>>>(X, E);
    vq_gather_kernel<<<NPIX / QP, 256>>>(X, E, out);
    if (out_size > ZQ_ELEMS)
        vq_loss_kernel<<<1, 1>>>(out);
}

// round 17
// speedup vs baseline: 1.1287x; 1.0018x over previous
#include <cuda_runtime.h>
#include <cuda_bf16.h>
#include <cstdint>

// Shapes (fixed for this problem)
#define B_   16
#define C_   256
#define HW_  4096
#define K_   1024
#define NPIX (B_ * HW_)          // 65536
#define ZQ_ELEMS (NPIX * C_)     // 16777216

// ---------------- scratch (static device arrays; no allocations) ------------
__device__ float  g_e2[K_];
__device__ int    g_idx[NPIX];
__device__ double g_loss;
__device__ __align__(16) __nv_bfloat16 g_xhi[(size_t)NPIX * C_];
__device__ __align__(16) __nv_bfloat16 g_xlo[(size_t)NPIX * C_];
__device__ __align__(16) __nv_bfloat16 g_ehi[K_ * C_];
__device__ __align__(16) __nv_bfloat16 g_elo[K_ * C_];
__device__ int g_rcnt;
__device__ int g_rpix[NPIX];

// ---------------- PTX helpers (sm_80+ features only; no 'a'-gated ops) ------
__device__ __forceinline__ uint32_t smem_u32(const void* p) {
    uint32_t a;
    asm("{ .reg .u64 t; cvta.to.shared.u64 t, %1; cvt.u32.u64 %0, t; }"
        : "=r"(a) : "l"(p));
    return a;
}
__device__ __forceinline__ void cp16(uint32_t dst, const void* src) {
    asm volatile("cp.async.cg.shared.global [%0], [%1], 16;"
                 :: "r"(dst), "l"(src) : "memory");
}
__device__ __forceinline__ void cp_commit() {
    asm volatile("cp.async.commit_group;" ::: "memory");
}
__device__ __forceinline__ void cp_wait1() {
    asm volatile("cp.async.wait_group 1;" ::: "memory");
}

// ---------------------------------------------------------------------------
// Prep 1: transpose x (b,c,hw) -> [pixel][c] bf16 hi/lo split.
// ---------------------------------------------------------------------------
__global__ __launch_bounds__(256)
void vq_prepx_kernel(const float* __restrict__ X) {
    __shared__ float tile[32][33];
    const int bi = blockIdx.x;
    const int b  = bi >> 10;
    const int t  = bi & 1023;
    const int c0 = (t >> 7) << 5;
    const int p0 = (t & 127) << 5;
    const int tid = threadIdx.x;

    #pragma unroll
    for (int it = 0; it < 4; ++it) {
        int idx = tid + it * 256;
        int c = idx >> 5, p = idx & 31;
        tile[c][p] = __ldg(X + ((size_t)b * C_ + c0 + c) * HW_ + p0 + p);
    }
    __syncthreads();
    #pragma unroll
    for (int it = 0; it < 4; ++it) {
        int idx = tid + it * 256;
        int p = idx >> 5, c = idx & 31;
        float v = tile[c][p];
        __nv_bfloat16 h = __float2bfloat16(v);
        __nv_bfloat16 l = __float2bfloat16(v - __bfloat162float(h));
        size_t dst = (size_t)(b * HW_ + p0 + p) * C_ + c0 + c;
        g_xhi[dst] = h;
        g_xlo[dst] = l;
    }
}

// ---------------------------------------------------------------------------
// Prep 2: embeddings -> bf16 hi/lo + fp32 squared norms; reset counters.
// ---------------------------------------------------------------------------
__global__ __launch_bounds__(256)
void vq_prepe_kernel(const float* __restrict__ E) {
    const int k = blockIdx.x, c = threadIdx.x;
    float v = __ldg(E + k * C_ + c);
    __nv_bfloat16 h = __float2bfloat16(v);
    g_ehi[k * C_ + c] = h;
    g_elo[k * C_ + c] = __float2bfloat16(v - __bfloat162float(h));
    float s = v * v;
    #pragma unroll
    for (int off = 16; off; off >>= 1)
        s += __shfl_down_sync(0xffffffffu, s, off);
    __shared__ float ws[8];
    if ((c & 31) == 0) ws[c >> 5] = s;
    __syncthreads();
    if (c < 8) {
        float t = ws[c];
        #pragma unroll
        for (int off = 4; off; off >>= 1)
            t += __shfl_down_sync(0xffu, t, off);
        if (c == 0) g_e2[k] = t;
    }
    if (k == 0 && c == 0) { g_loss = 0.0; g_rcnt = 0; }
}

// ---------------------------------------------------------------------------
// Main kernel: mma.sync bf16 split-GEMM + (v1,k1,v2) argmin with margin.
// Block: 256 threads = 8 warps (2 M x 4 N). Block tile: 128 pixels.
// 4 N-iterations of 256 codes; K = 3 bf16 passes x 256 dims, chunks of 64,
// cp.async double-buffered B. Distance d = e2[k] - 2 x.e.
// ---------------------------------------------------------------------------
#define GTP 128
// SMEM layout (bytes)
#define SM_A    0          // 2 splits x 65536 (128 p x 256 c bf16, swizzled)
#define SM_B    131072     // 2 bufs x 32768 (256 codes x 64 c bf16, swizzled)
#define SM_E2   196608     // 4096
#define SM_MV1  200704     // 128*4 floats
#define SM_MK1  202752
#define SM_MV2  204800
#define SM_TOT  206848

#define RESC_W 0.06f

__device__ __forceinline__ void load_b_chunk(uint32_t sb, int tid, int q, int buf) {
    const int nt = q >> 3, kc = (q >> 1) & 3, split = q & 1;
    const __nv_bfloat16* src = split ? g_elo : g_ehi;
    #pragma unroll
    for (int it = 0; it < 8; ++it) {
        int v = tid + it * 256;
        int row = v >> 3, g = v & 7;
        uint32_t gp = (uint32_t)(g ^ (row & 7));
        uint32_t dst = sb + SM_B + (uint32_t)buf * 32768u
                     + (uint32_t)row * 128u + gp * 16u;
        cp16(dst, src + ((size_t)(nt * 256 + row) * C_ + kc * 64 + g * 8));
    }
}

__global__ __launch_bounds__(256, 1)
void vq_gemm_kernel() {
    extern __shared__ char sm[];
    const uint32_t sb = smem_u32(sm);
    const int tid = threadIdx.x;
    const int lane = tid & 31, wid = tid >> 5;
    const int warp_m = wid >> 2, warp_n = wid & 3;
    const int n0 = blockIdx.x * GTP;

    // prologue: async-issue first two B chunks
    load_b_chunk(sb, tid, 0, 0); cp_commit();
    load_b_chunk(sb, tid, 1, 1); cp_commit();

    // stage A (hi + lo): [128 p][256 c] bf16, XOR-swizzled 16B granules
    #pragma unroll
    for (int it = 0; it < 32; ++it) {
        int v = tid + it * 256;          // 0..8191
        int s = v >> 12, rem = v & 4095;
        int p = rem >> 5, g = rem & 31;
        uint32_t gp = (uint32_t)((g & 24) | ((g ^ p) & 7));
        const uint4* src = (const uint4*)(s ? g_xlo : g_xhi);
        *(uint4*)(sm + SM_A + s * 65536 + p * 512 + gp * 16) =
            src[(size_t)(n0 + p) * 32 + g];
    }
    // stage e2
    for (int i = tid; i < K_; i += 256)
        ((float*)(sm + SM_E2))[i] = g_e2[i];

    float C[4][8][4];
    float sv1[8], sv2[8]; int sk1[8];
    #pragma unroll
    for (int i = 0; i < 8; ++i) { sv1[i] = 3.4e38f; sv2[i] = 3.4e38f; sk1[i] = 0; }

    int q = 0;
    #pragma unroll 1
    for (int nt = 0; nt < 4; ++nt) {
        #pragma unroll
        for (int mt = 0; mt < 4; ++mt)
            #pragma unroll
            for (int n8 = 0; n8 < 8; ++n8)
                #pragma unroll
                for (int e = 0; e < 4; ++e) C[mt][n8][e] = 0.f;

        #pragma unroll 1
        for (int kc = 0; kc < 4; ++kc) {
            #pragma unroll 1
            for (int split = 0; split < 2; ++split) {
                const int buf = q & 1;
                cp_wait1();
                __syncthreads();                 // chunk q ready for all warps
                const int npass = split ? 1 : 2; // hi-B: Ahi,Alo; lo-B: Ahi
                #pragma unroll 1
                for (int pass = 0; pass < npass; ++pass) {
                    const int asplit = (split == 0) ? pass : 0;
                    const uint32_t abase = sb + SM_A + (uint32_t)asplit * 65536u;
                    const uint32_t bbase = sb + SM_B + (uint32_t)buf * 32768u;
                    #pragma unroll
                    for (int kk = 0; kk < 4; ++kk) {
                        uint32_t a[4][4];
                        #pragma unroll
                        for (int mt = 0; mt < 4; ++mt) {
                            int p = warp_m * 64 + mt * 16 + (lane & 15);
                            int g = kc * 8 + kk * 2 + (lane >> 4);
                            uint32_t gp = (uint32_t)((g & 24) | ((g ^ p) & 7));
                            uint32_t addr = abase + (uint32_t)p * 512u + gp * 16u;
                            asm volatile(
                                "ldmatrix.sync.aligned.m8n8.x4.shared.b16 "
                                "{%0,%1,%2,%3}, [%4];"
                                : "=r"(a[mt][0]), "=r"(a[mt][1]),
                                  "=r"(a[mt][2]), "=r"(a[mt][3])
                                : "r"(addr));
                        }
                        uint32_t b[8][2];
                        #pragma unroll
                        for (int nq = 0; nq < 4; ++nq) {
                            int n = warp_n * 64 + nq * 16
                                  + ((lane >> 4) << 3) + (lane & 7);
                            int g = kk * 2 + ((lane >> 3) & 1);
                            uint32_t gp = (uint32_t)(g ^ (n & 7));
                            uint32_t addr = bbase + (uint32_t)n * 128u + gp * 16u;
                            asm volatile(
                                "ldmatrix.sync.aligned.m8n8.x4.shared.b16 "
                                "{%0,%1,%2,%3}, [%4];"
                                : "=r"(b[2 * nq][0]), "=r"(b[2 * nq][1]),
                                  "=r"(b[2 * nq + 1][0]), "=r"(b[2 * nq + 1][1])
                                : "r"(addr));
                        }
                        #pragma unroll
                        for (int mt = 0; mt < 4; ++mt)
                            #pragma unroll
                            for (int n8 = 0; n8 < 8; ++n8)
                                asm volatile(
                                    "mma.sync.aligned.m16n8k16.row.col.f32.bf16.bf16.f32 "
                                    "{%0,%1,%2,%3}, {%4,%5,%6,%7}, {%8,%9}, {%0,%1,%2,%3};"
                                    : "+f"(C[mt][n8][0]), "+f"(C[mt][n8][1]),
                                      "+f"(C[mt][n8][2]), "+f"(C[mt][n8][3])
                                    : "r"(a[mt][0]), "r"(a[mt][1]),
                                      "r"(a[mt][2]), "r"(a[mt][3]),
                                      "r"(b[n8][0]), "r"(b[n8][1]));
                    }
                }
                __syncthreads();                 // all done reading buf[q&1]
                if (q + 2 < 32) { load_b_chunk(sb, tid, q + 2, buf); cp_commit(); }
                ++q;
            }
        }

        // epilogue for this 256-code N-iteration
        const float* e2s = (const float*)(sm + SM_E2);
        #pragma unroll
        for (int mt = 0; mt < 4; ++mt) {
            #pragma unroll
            for (int n8 = 0; n8 < 8; ++n8) {
                int k = nt * 256 + warp_n * 64 + n8 * 8 + (lane & 3) * 2;
                float e20 = e2s[k], e21 = e2s[k + 1];
                #pragma unroll
                for (int h = 0; h < 2; ++h) {
                    int s = mt * 2 + h;
                    float d0 = fmaf(-2.f, C[mt][n8][2 * h], e20);
                    float d1 = fmaf(-2.f, C[mt][n8][2 * h + 1], e21);
                    if (d0 < sv1[s]) { sv2[s] = sv1[s]; sv1[s] = d0; sk1[s] = k; }
                    else if (d0 < sv2[s]) sv2[s] = d0;
                    if (d1 < sv1[s]) { sv2[s] = sv1[s]; sv1[s] = d1; sk1[s] = k + 1; }
                    else if (d1 < sv2[s]) sv2[s] = d1;
                }
            }
        }
    }

    // merge (v1,k1,v2) across the 4 lanes sharing each pixel row
    #pragma unroll
    for (int s = 0; s < 8; ++s) {
        float v1 = sv1[s], v2 = sv2[s]; int k1 = sk1[s];
        #pragma unroll
        for (int off = 1; off <= 2; off <<= 1) {
            float o1 = __shfl_xor_sync(0xffffffffu, v1, off);
            int   ok = __shfl_xor_sync(0xffffffffu, k1, off);
            float o2 = __shfl_xor_sync(0xffffffffu, v2, off);
            float m = fmaxf(v1, o1);
            if (o1 < v1 || (o1 == v1 && ok < k1)) { v1 = o1; k1 = ok; }
            v2 = fminf(fminf(v2, o2), m);
        }
        if ((lane & 3) == 0) {
            int pix = warp_m * 64 + (s >> 1) * 16 + (s & 1) * 8 + (lane >> 2);
            ((float*)(sm + SM_MV1))[pix * 4 + warp_n] = v1;
            ((int*)  (sm + SM_MK1))[pix * 4 + warp_n] = k1;
            ((float*)(sm + SM_MV2))[pix * 4 + warp_n] = v2;
        }
    }
    __syncthreads();
    // final merge across the 4 warp_n columns; emit index + rescue flag
    if (tid < GTP) {
        float v1 = 3.4e38f, v2 = 3.4e38f; int k1 = 0;
        #pragma unroll
        for (int w = 0; w < 4; ++w) {
            float o1 = ((float*)(sm + SM_MV1))[tid * 4 + w];
            int   ok = ((int*)  (sm + SM_MK1))[tid * 4 + w];
            float o2 = ((float*)(sm + SM_MV2))[tid * 4 + w];
            float m = fmaxf(v1, o1);
            if (o1 < v1 || (o1 == v1 && ok < k1)) { v1 = o1; k1 = ok; }
            v2 = fminf(fminf(v2, o2), m);
        }
        int pix = n0 + tid;
        g_idx[pix] = k1;
        if (v2 - v1 < RESC_W) {
            int r = atomicAdd(&g_rcnt, 1);
            g_rpix[r] = pix;
        }
    }
}

// ---------------------------------------------------------------------------
// Rescue: FULL exact fp32 scan (all 1024 codes) for near-margin pixels.
// Same fmaf-chain arithmetic as the proven scalar kernel.
// ---------------------------------------------------------------------------
__global__ __launch_bounds__(256)
void vq_rescue_kernel(const float* __restrict__ X, const float* __restrict__ E) {
    __shared__ float xr[C_];
    __shared__ float bv[256];
    __shared__ int   bk[256];
    const int t = threadIdx.x;

    for (int r = blockIdx.x; r < g_rcnt; r += gridDim.x) {
        const int pix = g_rpix[r];
        const int b = pix / HW_, hw = pix % HW_;
        if (t < C_) xr[t] = __ldg(X + ((size_t)b * C_ + t) * HW_ + hw);
        __syncthreads();

        float best = 3.4e38f; int bestk = 0;
        #pragma unroll 1
        for (int kk = 0; kk < 4; ++kk) {
            int k = t + kk * 256;
            const float* e = E + (size_t)k * C_;
            float acc = 0.f;
            #pragma unroll 8
            for (int c = 0; c < C_; ++c)
                acc = fmaf(xr[c], __ldg(e + c), acc);
            float d = fmaf(-2.f, acc, g_e2[k]);
            if (d < best || (d == best && k < bestk)) { best = d; bestk = k; }
        }
        bv[t] = best; bk[t] = bestk;
        __syncthreads();
        for (int s = 128; s; s >>= 1) {
            if (t < s) {
                if (bv[t + s] < bv[t] ||
                    (bv[t + s] == bv[t] && bk[t + s] < bk[t])) {
                    bv[t] = bv[t + s]; bk[t] = bk[t + s];
                }
            }
            __syncthreads();
        }
        if (t == 0) g_idx[pix] = bk[0];
        __syncthreads();
    }
}

// ---------------------------------------------------------------------------
// Gather z_q, transpose-write, accumulate loss.
// ---------------------------------------------------------------------------
#define QP 32

__global__ __launch_bounds__(256)
void vq_gather_kernel(const float* __restrict__ X, const float* __restrict__ E,
                      float* __restrict__ out) {
    __shared__ float s[QP][C_ + 5];
    __shared__ int ids[QP];

    const int tid = threadIdx.x;
    const int n0 = blockIdx.x * QP;
    if (tid < QP) ids[tid] = g_idx[n0 + tid];
    __syncthreads();

    #pragma unroll
    for (int l = 0; l < (QP * C_) / 256; ++l) {
        int ii = tid + l * 256;
        int q = ii >> 8, c = ii & 255;
        s[q][c] = __ldg(E + (size_t)ids[q] * C_ + c);
    }
    __syncthreads();

    const int b = n0 / HW_, p0 = n0 % HW_;
    const size_t obase = (size_t)b * C_ * HW_ + p0;
    const int q  = tid & 31;
    const int c0 = tid >> 5;

    float lsum = 0.f;
    #pragma unroll
    for (int l = 0; l < C_ / 8; ++l) {
        int c = c0 + l * 8;
        float zq = s[q][c];
        size_t a = obase + (size_t)c * HW_ + q;
        float xv = __ldg(X + a);
        out[a] = zq;
        float dd = xv - zq;
        lsum = fmaf(dd, dd, lsum);
    }

    #pragma unroll
    for (int off = 16; off; off >>= 1)
        lsum += __shfl_down_sync(0xffffffffu, lsum, off);
    __shared__ float ws[8];
    if ((tid & 31) == 0) ws[tid >> 5] = lsum;
    __syncthreads();
    if (tid < 8) {
        float v = ws[tid];
        #pragma unroll
        for (int off = 4; off; off >>= 1)
            v += __shfl_down_sync(0xffu, v, off);
        if (tid == 0) atomicAdd(&g_loss, (double)v);
    }
}

__global__ void vq_loss_kernel(float* __restrict__ out) {
    out[ZQ_ELEMS] = (float)(2.0 * g_loss / (double)ZQ_ELEMS);
}

// ---------------------------------------------------------------------------
extern "C" void kernel_launch(void* const* d_in, const int* in_sizes, int n_in,
                              void* d_out, int out_size) {
    const float* X = (const float*)d_in[0];
    const float* E = (const float*)d_in[1];
    float* out = (float*)d_out;

    cudaFuncSetAttribute(vq_gemm_kernel,
                         cudaFuncAttributeMaxDynamicSharedMemorySize, SM_TOT);

    vq_prepx_kernel<<<16384, 256>>>(X);
    vq_prepe_kernel<<<K_, 256>>>(E);
    vq_gemm_kernel<<<NPIX / GTP, 256, SM_TOT>>>();
    vq_rescue_kernel<<<1024, 256>>>(X, E);
    vq_gather_kernel<<<NPIX / QP, 256>>>(X, E, out);
    if (out_size > ZQ_ELEMS)
        vq_loss_kernel<<<1, 1>>>(out);
}